// round 6
// baseline (speedup 1.0000x reference)
#include <cuda_runtime.h>
#include <cstdint>

// Problem constants
#define HWX   65536          // 256*256
#define NPIX  131072ul       // 2*256*256
#define CCH   320
#define SPL   160

// Scratch (static __device__ — no allocations allowed)
__device__ float g_mean[131072];
__device__ float g_rstd[131072];
__device__ float g_wc[960 * 320];        // combined (w_* @ conv_half)
__device__ float g_bc[960];              // combined biases
__device__ float g_qkv[960ul * 131072ul];   // GEMM output: rows 0..479 = h(q,k,v), 480..959 = v(q,k,v)
__device__ float g_qkvT[480ul * 131072ul];  // vertical qkv, H-major
__device__ float g_avs[160ul * 131072ul];   // vertical attn out, [c][b][w][h]

// ---------------------------------------------------------------------------
// packed fp32x2 FMA (sm_103a FFMA2) — 2x fp32 fma throughput
// ---------------------------------------------------------------------------
__device__ __forceinline__ float2 ffma2(float2 a, float2 b, float2 c) {
    float2 d;
    asm("{\n\t"
        ".reg .b64 ra, rb, rc, rd;\n\t"
        "mov.b64 ra, {%2, %3};\n\t"
        "mov.b64 rb, {%4, %5};\n\t"
        "mov.b64 rc, {%6, %7};\n\t"
        "fma.rn.f32x2 rd, ra, rb, rc;\n\t"
        "mov.b64 {%0, %1}, rd;\n\t"
        "}"
        : "=f"(d.x), "=f"(d.y)
        : "f"(a.x), "f"(a.y), "f"(b.x), "f"(b.y), "f"(c.x), "f"(c.y));
    return d;
}

// ---------------------------------------------------------------------------
// 1) Per-pixel LayerNorm stats over channels
// ---------------------------------------------------------------------------
__global__ void ln_stats_kernel(const float* __restrict__ x) {
    int p  = blockIdx.x * 256 + threadIdx.x;     // 0..131071
    int b  = p >> 16;
    int hw = p & 65535;
    const float* xp = x + (size_t)b * CCH * HWX + hw;
    float s = 0.f, s2 = 0.f;
#pragma unroll 4
    for (int c = 0; c < CCH; c++) {
        float v = __ldg(xp + (size_t)c * HWX);
        s += v; s2 += v * v;
    }
    float mu  = s * (1.f / 320.f);
    float var = s2 * (1.f / 320.f) - mu * mu;
    g_mean[p] = mu;
    g_rstd[p] = rsqrtf(var + 1e-5f);
}

// ---------------------------------------------------------------------------
// 2) Fold conv into QKV: Wc[r][c] = sum_d w_g[ro][d] * conv_w[half*160+d][c]
//    bc[r] = b_g[ro] + sum_d w_g[ro][d] * conv_b[half*160+d]
//    row groups: 0 qh, 1 kh, 2 vh, 3 qv, 4 kv, 5 vv  (160 rows each)
// ---------------------------------------------------------------------------
__global__ void combine_w_kernel(
    const float* __restrict__ conv_w, const float* __restrict__ conv_b,
    const float* w0, const float* b0, const float* w1, const float* b1,
    const float* w2, const float* b2, const float* w3, const float* b3,
    const float* w4, const float* b4, const float* w5, const float* b5)
{
    int r  = blockIdx.x;           // 0..959
    int g  = r / 160, ro = r % 160;
    const float* wg; const float* bg;
    switch (g) {
        case 0: wg = w0; bg = b0; break;
        case 1: wg = w1; bg = b1; break;
        case 2: wg = w2; bg = b2; break;
        case 3: wg = w3; bg = b3; break;
        case 4: wg = w4; bg = b4; break;
        default: wg = w5; bg = b5; break;
    }
    int half = (g >= 3) ? 1 : 0;
    __shared__ float wrow[160];
    if (threadIdx.x < 160) wrow[threadIdx.x] = __ldg(wg + ro * 160 + threadIdx.x);
    __syncthreads();
    int c = threadIdx.x;           // 0..319
    const float* cw = conv_w + (size_t)half * 160 * 320 + c;
    float s = 0.f;
#pragma unroll 4
    for (int d = 0; d < 160; d++)
        s += wrow[d] * __ldg(cw + d * 320);
    g_wc[r * 320 + c] = s;
    if (c == 0) {
        float sb = __ldg(bg + ro);
        const float* cb = conv_b + half * 160;
        for (int d = 0; d < 160; d++) sb += wrow[d] * __ldg(cb + d);
        g_bc[r] = sb;
    }
}

// ---------------------------------------------------------------------------
// 3) GEMM: qkv[960][131072] = Wc @ LN(x) + bc  (LN applied on B-tile load)
//    BM=64, BN=128, BK=16, 256 threads, thread tile 8x4, f32x2 accumulators
// ---------------------------------------------------------------------------
__global__ void __launch_bounds__(256) gemm_qkv_kernel(
    const float* __restrict__ x,
    const float* __restrict__ lnw, const float* __restrict__ lnb)
{
    __shared__ float As[16][68];     // [k][m], padded
    __shared__ float Bs[16][128];    // [k][n]

    int m0  = blockIdx.x * 64;
    int n0  = blockIdx.y * 128;
    int tid = threadIdx.x;
    int tx  = tid & 31;              // n group (4 cols)
    int ty  = tid >> 5;              // m group (8 rows)

    int b   = n0 >> 16;
    int hw0 = n0 & 65535;
    const float* xb = x + (size_t)b * CCH * HWX + hw0;

    int jn    = tid & 127;           // fixed B-load column for this thread
    int kpar  = tid >> 7;            // 0/1
    float meanv = g_mean[n0 + jn];
    float rstdv = g_rstd[n0 + jn];

    float2 acc[8][2];
#pragma unroll
    for (int i = 0; i < 8; i++) { acc[i][0] = make_float2(0.f, 0.f); acc[i][1] = make_float2(0.f, 0.f); }

    for (int k0 = 0; k0 < 320; k0 += 16) {
        // stage A: 64x16
#pragma unroll
        for (int i = 0; i < 4; i++) {
            int idx = tid + i * 256;
            int kk = idx & 15, m = idx >> 4;
            As[kk][m] = __ldg(&g_wc[(m0 + m) * 320 + k0 + kk]);
        }
        // stage B: 16x128 with LN applied
#pragma unroll
        for (int i = 0; i < 8; i++) {
            int kk = kpar + 2 * i;
            float v = __ldg(xb + (size_t)(k0 + kk) * HWX + jn);
            Bs[kk][jn] = fmaf((v - meanv) * rstdv, __ldg(lnw + k0 + kk), __ldg(lnb + k0 + kk));
        }
        __syncthreads();
#pragma unroll
        for (int kk = 0; kk < 16; kk++) {
            float4 a0 = *(const float4*)&As[kk][ty * 8];
            float4 a1 = *(const float4*)&As[kk][ty * 8 + 4];
            float4 bq = *(const float4*)&Bs[kk][tx * 4];
            float2 bv0 = make_float2(bq.x, bq.y);
            float2 bv1 = make_float2(bq.z, bq.w);
            float a[8] = {a0.x, a0.y, a0.z, a0.w, a1.x, a1.y, a1.z, a1.w};
#pragma unroll
            for (int i = 0; i < 8; i++) {
                float2 av = make_float2(a[i], a[i]);
                acc[i][0] = ffma2(av, bv0, acc[i][0]);
                acc[i][1] = ffma2(av, bv1, acc[i][1]);
            }
        }
        __syncthreads();
    }
#pragma unroll
    for (int i = 0; i < 8; i++) {
        int m = m0 + ty * 8 + i;
        float bias = g_bc[m];
        float4 o = make_float4(acc[i][0].x + bias, acc[i][0].y + bias,
                               acc[i][1].x + bias, acc[i][1].y + bias);
        *(float4*)&g_qkv[(size_t)m * NPIX + n0 + tx * 4] = o;
    }
}

// ---------------------------------------------------------------------------
// 4) Transpose vertical qkv rows (960 matrices of 256x256) into H-major order
// ---------------------------------------------------------------------------
__global__ void transpose_qkv_kernel() {
    __shared__ float tile[32][33];
    int m = blockIdx.z;                       // 0..959  (= r*2 + b)
    const float* s = g_qkv + 480ul * NPIX + (size_t)m * HWX;
    float* d       = g_qkvT + (size_t)m * HWX;
    int x0 = blockIdx.x * 32, y0 = blockIdx.y * 32;
    int tx = threadIdx.x, ty = threadIdx.y;
#pragma unroll
    for (int i = 0; i < 4; i++)
        tile[ty + i * 8][tx] = s[(size_t)(y0 + ty + i * 8) * 256 + x0 + tx];
    __syncthreads();
#pragma unroll
    for (int i = 0; i < 4; i++)
        d[(size_t)(x0 + ty + i * 8) * 256 + y0 + tx] = tile[tx][ty + i * 8];
}

// ---------------------------------------------------------------------------
// 5) Axial attention. One block = (head, sequence). 256 threads = 256 queries.
//    K/V staged in smem in 128-key chunks.
//    VMODE=0: reads g_qkv (device symbol, resolved IN device code),
//             writes d_out batches 0..1 (coalesced over w).
//    VMODE=1: reads g_qkvT, writes g_avs [c][b][w][h] (coalesced over h).
//    NOTE: qkv source MUST be selected inside device code — passing a
//    __device__ symbol as a host-side kernel argument yields the host
//    shadow (readable-as-zeros via GB300 ATS), which was the R0-R4 bug.
// ---------------------------------------------------------------------------
template <int VMODE>
__global__ void __launch_bounds__(256) attn_kernel(float* __restrict__ out)
{
    __shared__ float Ks[128 * 36];
    __shared__ float Vs[128 * 36];
    int hd  = blockIdx.x;        // 0..4
    int seq = blockIdx.y;        // 0..511
    int t   = threadIdx.x;       // query position

    const float* qkv = (VMODE == 0) ? g_qkv : g_qkvT;

    const float* qb = qkv + (size_t)(hd * 32) * NPIX + (size_t)seq * 256 + t;
    const float* kb = qkv + (size_t)(160 + hd * 32) * NPIX + (size_t)seq * 256;
    const float* vb = qkv + (size_t)(320 + hd * 32) * NPIX + (size_t)seq * 256;

    float2 q2[16];
#pragma unroll
    for (int c = 0; c < 16; c++) {
        q2[c].x = __ldg(qb + (size_t)(2 * c) * NPIX);
        q2[c].y = __ldg(qb + (size_t)(2 * c + 1) * NPIX);
    }

    float mx = -1e30f, l = 0.f;
    float2 acc[16];
#pragma unroll
    for (int c = 0; c < 16; c++) acc[c] = make_float2(0.f, 0.f);
    const float scale = 0.17677669529663688f;   // 1/sqrt(32)

    for (int chunk = 0; chunk < 2; chunk++) {
        int j0 = chunk * 128;
        __syncthreads();
#pragma unroll
        for (int i = 0; i < 16; i++) {
            int idx = t + i * 256;
            int pos = idx & 127, c = idx >> 7;
            Ks[pos * 36 + c] = __ldg(kb + (size_t)c * NPIX + j0 + pos);
            Vs[pos * 36 + c] = __ldg(vb + (size_t)c * NPIX + j0 + pos);
        }
        __syncthreads();
        for (int j = 0; j < 128; j++) {
            const float4* k4 = (const float4*)(Ks + j * 36);
            const float4* v4 = (const float4*)(Vs + j * 36);
            float2 d2 = make_float2(0.f, 0.f);
#pragma unroll
            for (int c = 0; c < 8; c++) {
                float4 kv = k4[c];
                d2 = ffma2(q2[2 * c],     make_float2(kv.x, kv.y), d2);
                d2 = ffma2(q2[2 * c + 1], make_float2(kv.z, kv.w), d2);
            }
            float s = (d2.x + d2.y) * scale;
            if (s > mx) {                       // rare rescale (online softmax)
                float corr = __expf(mx - s);
                mx = s; l *= corr;
#pragma unroll
                for (int c = 0; c < 16; c++) { acc[c].x *= corr; acc[c].y *= corr; }
            }
            float p = __expf(s - mx);
            l += p;
            float2 pp = make_float2(p, p);
#pragma unroll
            for (int c = 0; c < 8; c++) {
                float4 vv = v4[c];
                acc[2 * c]     = ffma2(pp, make_float2(vv.x, vv.y), acc[2 * c]);
                acc[2 * c + 1] = ffma2(pp, make_float2(vv.z, vv.w), acc[2 * c + 1]);
            }
        }
    }
    float rl = 1.f / l;
    if (VMODE == 0) {
        int b = seq >> 8, h = seq & 255;
        float* o = out + (size_t)(b * 160 + hd * 32) * HWX + h * 256 + t;
#pragma unroll
        for (int c = 0; c < 16; c++) {
            o[(size_t)(2 * c) * HWX]     = acc[c].x * rl;
            o[(size_t)(2 * c + 1) * HWX] = acc[c].y * rl;
        }
    } else {
        float* o = g_avs + (size_t)(hd * 32) * NPIX + (size_t)seq * 256 + t;
#pragma unroll
        for (int c = 0; c < 16; c++) {
            o[(size_t)(2 * c) * NPIX]     = acc[c].x * rl;
            o[(size_t)(2 * c + 1) * NPIX] = acc[c].y * rl;
        }
    }
}

// ---------------------------------------------------------------------------
// 6) Final transpose of vertical attention output into d_out batches 2..3:
//    out[2+b][c][h][w] = g_avs[c][b][w][h]
// ---------------------------------------------------------------------------
__global__ void transpose_av_kernel(float* __restrict__ outp) {
    __shared__ float tile[32][33];
    int z = blockIdx.z;                // dst mat index: b*160 + c, 0..319
    int b = z / 160, c = z % 160;
    const float* s = g_avs + (size_t)(c * 2 + b) * HWX;
    float* d = outp + 2ul * 160ul * HWX + (size_t)z * HWX;
    int x0 = blockIdx.x * 32, y0 = blockIdx.y * 32;
    int tx = threadIdx.x, ty = threadIdx.y;
#pragma unroll
    for (int i = 0; i < 4; i++)
        tile[ty + i * 8][tx] = s[(size_t)(y0 + ty + i * 8) * 256 + x0 + tx];
    __syncthreads();
#pragma unroll
    for (int i = 0; i < 4; i++)
        d[(size_t)(x0 + ty + i * 8) * 256 + y0 + tx] = tile[tx][ty + i * 8];
}

// ---------------------------------------------------------------------------
extern "C" void kernel_launch(void* const* d_in, const int* in_sizes, int n_in,
                              void* d_out, int out_size)
{
    const float* x      = (const float*)d_in[0];
    const float* lnw    = (const float*)d_in[1];
    const float* lnb    = (const float*)d_in[2];
    const float* conv_w = (const float*)d_in[3];
    const float* conv_b = (const float*)d_in[4];
    float* out = (float*)d_out;

    ln_stats_kernel<<<512, 256>>>(x);
    combine_w_kernel<<<960, 320>>>(conv_w, conv_b,
        (const float*)d_in[5],  (const float*)d_in[6],
        (const float*)d_in[7],  (const float*)d_in[8],
        (const float*)d_in[9],  (const float*)d_in[10],
        (const float*)d_in[11], (const float*)d_in[12],
        (const float*)d_in[13], (const float*)d_in[14],
        (const float*)d_in[15], (const float*)d_in[16]);
    gemm_qkv_kernel<<<dim3(15, 1024), 256>>>(x, lnw, lnb);
    transpose_qkv_kernel<<<dim3(8, 8, 960), dim3(32, 8)>>>();

    // horizontal attention: reads g_qkv rows 0..479, writes d_out batches 0..1
    attn_kernel<0><<<dim3(5, 512), 256>>>(out);
    // vertical attention: reads g_qkvT rows 0..479, writes g_avs
    attn_kernel<1><<<dim3(5, 512), 256>>>(out);
    // final transpose into d_out batches 2..3
    transpose_av_kernel<<<dim3(8, 8, 320), dim3(32, 8)>>>(out);
}